// round 7
// baseline (speedup 1.0000x reference)
#include <cuda_runtime.h>
#include <cstdint>

#define SQ 512
#define NSEQ 512
#define CM 64
#define CZ 128
#define NH 8
#define EPS 1e-5f

// Scratch (device globals: allocation-free)
__device__ float g_w[(size_t)SQ * NH * SQ];        // raw logits [i][h][j]
__device__ float g_whf[(size_t)SQ * NH * SQ];      // w hi, A-frag layout [I][h][jg][lane][4]
__device__ float g_wlf[(size_t)SQ * NH * SQ];      // w lo, same layout
__device__ float g_vTf[(size_t)CM * NSEQ * SQ];    // v, B-frag layout [h][ndg][jg][lane][2]
__device__ float g_gT[(size_t)CM * NSEQ * SQ];     // gate [(c*512+n)*512 + s]
__device__ float g_o2[(size_t)CM * NSEQ * SQ];     // gated o, [(c*512+n)*512 + i]

__device__ __forceinline__ float warp_sum(float v) {
#pragma unroll
    for (int o = 16; o > 0; o >>= 1) v += __shfl_xor_sync(0xffffffffu, v, o);
    return v;
}
__device__ __forceinline__ uint32_t smem_u32(const void* p) {
    uint32_t a;
    asm("{ .reg .u64 t; cvta.to.shared.u64 t, %1; cvt.u32.u64 %0, t; }" : "=r"(a) : "l"(p));
    return a;
}
__device__ __forceinline__ float tf32rn(float x) {
    uint32_t r;
    asm("cvt.rna.tf32.f32 %0, %1;" : "=r"(r) : "f"(x));
    return __uint_as_float(r);
}
__device__ __forceinline__ void mma_tf32(float* d, const uint32_t* a,
                                         uint32_t b0, uint32_t b1) {
    asm volatile(
        "mma.sync.aligned.m16n8k8.row.col.f32.tf32.tf32.f32 "
        "{%0,%1,%2,%3}, {%4,%5,%6,%7}, {%8,%9}, {%0,%1,%2,%3};"
        : "+f"(d[0]), "+f"(d[1]), "+f"(d[2]), "+f"(d[3])
        : "r"(a[0]), "r"(a[1]), "r"(a[2]), "r"(a[3]), "r"(b0), "r"(b1));
}
#define CP_ASYNC16(dst, src) \
    asm volatile("cp.async.cg.shared.global [%0], [%1], 16;" :: "r"(dst), "l"(src))
#define CP_COMMIT() asm volatile("cp.async.commit_group;")
#define CP_WAIT(n)  asm volatile("cp.async.wait_group %0;" :: "n"(n))

// swizzled float index (used by vg phase-2 only)
__device__ __forceinline__ int fidx32(int row, int k) {
    return row * 32 + ((((k >> 2) ^ (row & 7)) << 2) | (k & 3));
}

// ---------------------------------------------------------------------------
// Kernel 1: b[i,h,j] = LN(z[i,j,:]) . W_b[h,:] -> g_w.  All-register version:
// warp per row (4 rows sequential), Wb held in registers, shuffle reductions.
// ---------------------------------------------------------------------------
__global__ __launch_bounds__(256) void bias_ln_kernel(
    const float* __restrict__ z, const float* __restrict__ lnw,
    const float* __restrict__ lnb, const float* __restrict__ Wb)
{
    __shared__ float swb[NH * CZ];
    int tid = threadIdx.x, warp = tid >> 5, lane = tid & 31;
#pragma unroll
    for (int i = tid; i < NH * CZ; i += 256) swb[i] = Wb[i];
    __syncthreads();

    float4 wbr[8];
#pragma unroll
    for (int h = 0; h < 8; ++h)
        wbr[h] = *(const float4*)(swb + h * CZ + lane * 4);
    float4 lw = *(const float4*)(lnw + lane * 4);
    float4 lb = *(const float4*)(lnb + lane * 4);

    size_t R0 = (size_t)blockIdx.x * 32 + warp * 4;
#pragma unroll
    for (int rr = 0; rr < 4; ++rr) {
        size_t row = R0 + rr;
        float4 x = *(const float4*)(z + row * CZ + lane * 4);
        float s = warp_sum(x.x + x.y + x.z + x.w);
        float mu = s * (1.0f / CZ);
        float d0 = x.x - mu, d1 = x.y - mu, d2 = x.z - mu, d3 = x.w - mu;
        float q = warp_sum(d0 * d0 + d1 * d1 + d2 * d2 + d3 * d3);
        float rs = rsqrtf(q * (1.0f / CZ) + EPS);
        float n0 = d0 * rs * lw.x + lb.x;
        float n1 = d1 * rs * lw.y + lb.y;
        float n2 = d2 * rs * lw.z + lb.z;
        float n3 = d3 * rs * lw.w + lb.w;

        int i = (int)(row >> 9), j = (int)(row & 511);
        float* dst = g_w + (size_t)i * 4096 + j;
#pragma unroll
        for (int h = 0; h < 8; ++h) {
            float p = n0 * wbr[h].x + n1 * wbr[h].y + n2 * wbr[h].z + n3 * wbr[h].w;
            p = warp_sum(p);
            if (lane == h) dst[h * 512] = p;
        }
    }
}

// ---------------------------------------------------------------------------
// Kernel 2: softmax over j; emits A-fragment-layout hi/lo slabs.
// ---------------------------------------------------------------------------
#define SMX_SMEMB (2 * 8704 * 4)
__global__ __launch_bounds__(256, 1) void softmax_kernel()
{
    extern __shared__ float sx[];
    float* smh = sx;            // [j*17 + i_loc]
    float* sml = sx + 8704;
    int tid = threadIdx.x;
    int row = tid >> 4, l = tid & 15;
    int I = blockIdx.x >> 3, h = blockIdx.x & 7;
    const float* src = g_w + ((size_t)(I * 16 + row)) * 4096 + h * 512;

    float w[32];
    float mx = -1e30f;
#pragma unroll
    for (int jj = 0; jj < 32; ++jj) {
        w[jj] = src[jj * 16 + l];
        mx = fmaxf(mx, w[jj]);
    }
#pragma unroll
    for (int o = 8; o > 0; o >>= 1) mx = fmaxf(mx, __shfl_xor_sync(0xffffffffu, mx, o));
    float sum = 0.f;
#pragma unroll
    for (int jj = 0; jj < 32; ++jj) {
        w[jj] = __expf(w[jj] - mx);
        sum += w[jj];
    }
#pragma unroll
    for (int o = 8; o > 0; o >>= 1) sum += __shfl_xor_sync(0xffffffffu, sum, o);
    float inv = 1.0f / sum;
#pragma unroll
    for (int jj = 0; jj < 32; ++jj) {
        int j = jj * 16 + l;
        float wv = w[jj] * inv;
        float hv = tf32rn(wv);
        smh[j * 17 + row] = hv;
        sml[j * 17 + row] = wv - hv;
    }
    __syncthreads();

    float* dh = g_whf + (size_t)(I * 8 + h) * 8192;
    float* dl = g_wlf + (size_t)(I * 8 + h) * 8192;
#pragma unroll
    for (int it = 0; it < 8; ++it) {
        int u = it * 256 + tid;
        int jg = u >> 5, lane = u & 31;
        float4 vh, vl;
#pragma unroll
        for (int idx = 0; idx < 4; ++idx) {
            int il = (lane >> 2) + (idx & 1) * 8;
            int j = jg * 8 + ((idx >> 1) & 1) * 4 + (lane & 3);
            (&vh.x)[idx] = smh[j * 17 + il];
            (&vl.x)[idx] = sml[j * 17 + il];
        }
        *(float4*)(dh + u * 4) = vh;
        *(float4*)(dl + u * 4) = vl;
    }
}

// ---------------------------------------------------------------------------
// Kernel 3: fused LN(m) -> mma -> vT (B-frag layout) + gate (transposed).
// ---------------------------------------------------------------------------
#define VG_AH 0
#define VG_AL 8192
#define VG_BH 16384
#define VG_SMEMF 24576
#define VG_SMEMB (VG_SMEMF * 4)

__global__ __launch_bounds__(256, 1) void vg_kernel(
    const float* __restrict__ m, const float* __restrict__ lnw,
    const float* __restrict__ lnb, const float* __restrict__ Wv,
    const float* __restrict__ Wg)
{
    extern __shared__ float sm[];
    int tid = threadIdx.x, wid = tid >> 5, lane = tid & 31;
    int g = lane >> 2, tg = lane & 3;
    int n = blockIdx.x, s0 = blockIdx.y * 128;

    {   // phase 1: LN + split to swizzled smem
        int row = tid >> 1, half = tid & 1;
        const float* src = m + ((size_t)(s0 + row) * 512 + n) * CM + half * 32;
        float v[32];
        float s = 0.f, q = 0.f;
#pragma unroll
        for (int qd = 0; qd < 8; ++qd) {
            float4 a = *(const float4*)(src + qd * 4);
            v[qd * 4 + 0] = a.x; v[qd * 4 + 1] = a.y;
            v[qd * 4 + 2] = a.z; v[qd * 4 + 3] = a.w;
            s += a.x + a.y + a.z + a.w;
            q += a.x * a.x + a.y * a.y + a.z * a.z + a.w * a.w;
        }
        s += __shfl_xor_sync(0xffffffffu, s, 1);
        q += __shfl_xor_sync(0xffffffffu, q, 1);
        float mu = s * (1.0f / CM);
        float var = q * (1.0f / CM) - mu * mu;
        float rs = rsqrtf(var + EPS);
#pragma unroll
        for (int qd = 0; qd < 8; ++qd) {
            int kq = half * 8 + qd;
            float xs[4];
#pragma unroll
            for (int t = 0; t < 4; ++t) {
                int k = kq * 4 + t;
                xs[t] = (v[qd * 4 + t] - mu) * rs * __ldg(lnw + k) + __ldg(lnb + k);
            }
            float4 hi = make_float4(tf32rn(xs[0]), tf32rn(xs[1]), tf32rn(xs[2]), tf32rn(xs[3]));
            float4 lo = make_float4(xs[0] - hi.x, xs[1] - hi.y, xs[2] - hi.z, xs[3] - hi.w);
            int f4 = (kq >> 3) * 1024 + row * 8 + ((kq & 7) ^ (row & 7));
            *(float4*)(sm + VG_AH + f4 * 4) = hi;
            *(float4*)(sm + VG_AL + f4 * 4) = lo;
        }
        const float* wsrc = (row < 64) ? (Wv + row * 64) : (Wg + (row - 64) * 64);
#pragma unroll
        for (int qd = 0; qd < 8; ++qd) {
            int kq = half * 8 + qd;
            float4 a = *(const float4*)(wsrc + kq * 4);
            float4 hi = make_float4(tf32rn(a.x), tf32rn(a.y), tf32rn(a.z), tf32rn(a.w));
            int f4 = (kq >> 3) * 1024 + row * 8 + ((kq & 7) ^ (row & 7));
            *(float4*)(sm + VG_BH + f4 * 4) = hi;
        }
    }
    __syncthreads();

    // phase 2: mma
    int wi = (wid & 3) * 32, wn = (wid >> 2) * 64;
    float acc[2][8][4];
#pragma unroll
    for (int mt = 0; mt < 2; ++mt)
#pragma unroll
        for (int nt = 0; nt < 8; ++nt)
#pragma unroll
            for (int r = 0; r < 4; ++r) acc[mt][nt][r] = 0.f;

#pragma unroll
    for (int k8 = 0; k8 < 8; ++k8) {
        int kb = k8 * 8;
        int sec = (kb >> 5) * 4096;
        int kl = kb & 31;
        uint32_t ah[2][4], al[2][4];
#pragma unroll
        for (int mt = 0; mt < 2; ++mt) {
            int r0 = wi + mt * 16 + g;
            ah[mt][0] = __float_as_uint(sm[VG_AH + sec + fidx32(r0, kl + tg)]);
            ah[mt][1] = __float_as_uint(sm[VG_AH + sec + fidx32(r0 + 8, kl + tg)]);
            ah[mt][2] = __float_as_uint(sm[VG_AH + sec + fidx32(r0, kl + 4 + tg)]);
            ah[mt][3] = __float_as_uint(sm[VG_AH + sec + fidx32(r0 + 8, kl + 4 + tg)]);
            al[mt][0] = __float_as_uint(sm[VG_AL + sec + fidx32(r0, kl + tg)]);
            al[mt][1] = __float_as_uint(sm[VG_AL + sec + fidx32(r0 + 8, kl + tg)]);
            al[mt][2] = __float_as_uint(sm[VG_AL + sec + fidx32(r0, kl + 4 + tg)]);
            al[mt][3] = __float_as_uint(sm[VG_AL + sec + fidx32(r0 + 8, kl + 4 + tg)]);
        }
#pragma unroll
        for (int nt = 0; nt < 8; ++nt) {
            int n0 = wn + nt * 8 + g;
            uint32_t b0 = __float_as_uint(sm[VG_BH + sec + fidx32(n0, kl + tg)]);
            uint32_t b1 = __float_as_uint(sm[VG_BH + sec + fidx32(n0, kl + 4 + tg)]);
#pragma unroll
            for (int mt = 0; mt < 2; ++mt) {
                mma_tf32(acc[mt][nt], ah[mt], b0, b1);
                mma_tf32(acc[mt][nt], al[mt], b0, b1);
            }
        }
    }
    __syncthreads();

    // phase 3: epilogue.  Cs = v [c 64][132 rows]; Cg2 = gate [c 64][132 rows]
    float* Cs = sm;
    float* Cg2 = sm + 8448;
#pragma unroll
    for (int mt = 0; mt < 2; ++mt) {
        int r = wi + mt * 16 + g;
#pragma unroll
        for (int nt = 0; nt < 8; ++nt) {
            int col = wn + nt * 8 + 2 * tg;
            if (wid < 4) {
                Cs[col * 132 + r]            = acc[mt][nt][0];
                Cs[(col + 1) * 132 + r]      = acc[mt][nt][1];
                Cs[col * 132 + r + 8]        = acc[mt][nt][2];
                Cs[(col + 1) * 132 + r + 8]  = acc[mt][nt][3];
            } else {
                int cl = col - 64;
                Cg2[cl * 132 + r]            = 1.0f / (1.0f + __expf(-acc[mt][nt][0]));
                Cg2[(cl + 1) * 132 + r]      = 1.0f / (1.0f + __expf(-acc[mt][nt][1]));
                Cg2[cl * 132 + r + 8]        = 1.0f / (1.0f + __expf(-acc[mt][nt][2]));
                Cg2[(cl + 1) * 132 + r + 8]  = 1.0f / (1.0f + __expf(-acc[mt][nt][3]));
            }
        }
    }
    __syncthreads();
    // vT -> B-frag layout: nd = d*512+n; ndg = d*64+(n>>3); gpos = n&7
#pragma unroll
    for (int it = 0; it < 16; ++it) {
        int u = it * 256 + tid;
        int c = u >> 6, rem = u & 63;
        int jgl = rem >> 2, j3 = rem & 3;
        int sl = jgl * 8 + j3;
        float v0 = tf32rn(Cs[c * 132 + sl]);
        float v1 = tf32rn(Cs[c * 132 + sl + 4]);
        int d = c & 7, hh = c >> 3;
        int ndg = d * 64 + (n >> 3);
        int gpos = n & 7;
        size_t off = (((size_t)hh * 512 + ndg) * 64 + (size_t)((s0 >> 3) + jgl)) * 64
                   + (gpos * 4 + j3) * 2;
        *(float2*)(g_vTf + off) = make_float2(v0, v1);
    }
    // gate transposed: g_gT[(c*512+n)*512 + s]
#pragma unroll
    for (int it = 0; it < 8; ++it) {
        int idx = it * 256 + tid;
        int c = idx >> 5, sq = idx & 31;
        *(float4*)(g_gT + ((size_t)c * 512 + n) * 512 + s0 + sq * 4) =
            *(const float4*)(Cg2 + c * 132 + sq * 4);
    }
}

// ---------------------------------------------------------------------------
// Kernel 4: pwa 2-term TF32 mma GEMM, 3-stage cp.async, gate fused in epilogue.
// Block 256 thr, 2 CTA/SM: M=128(i) x N=128(nd), K=512, kc=16.
// Stage (floats): AH 2048 | AL 2048 | B 2048 = 24KB; 3 stages = 72KB.
// ---------------------------------------------------------------------------
#define PW_STGF 6144
#define PW_STGB 24576
#define PW_SMEMB (3 * PW_STGB)

__device__ __forceinline__ void pw_ldstage(uint32_t sb, int tid,
                                           const float* Ah_g, const float* Al_g,
                                           const float* Bg, int chunk)
{
    int jg0 = chunk * 2;
#pragma unroll
    for (int it = 0; it < 2; ++it) {       // A: 512 float4 each (hi, lo)
        int t = it * 256 + tid;
        int Igl = t >> 6, rem = t & 63;
        int jgl = rem >> 5, part = rem & 31;
        size_t src = (size_t)Igl * 65536 + (jg0 + jgl) * 128 + part * 4;
        uint32_t dstf = (uint32_t)((Igl * 2 + jgl) * 128 + part * 4);
        CP_ASYNC16(sb + dstf * 4, Ah_g + src);
        CP_ASYNC16(sb + 8192 + dstf * 4, Al_g + src);
    }
#pragma unroll
    for (int it = 0; it < 2; ++it) {       // B: 512 float4
        int t = it * 256 + tid;
        int ndgl = t >> 5, rem = t & 31;
        int jgl = rem >> 4, part = rem & 15;
        size_t src = (size_t)ndgl * 4096 + (jg0 + jgl) * 64 + part * 4;
        uint32_t dstf = (uint32_t)((ndgl * 2 + jgl) * 64 + part * 4);
        CP_ASYNC16(sb + 16384 + dstf * 4, Bg + src);
    }
}

__global__ __launch_bounds__(256, 2) void pwa_mma_kernel()
{
    extern __shared__ float sm[];
    uint32_t sbase = smem_u32(sm);
    int tid = threadIdx.x, wid = tid >> 5, lane = tid & 31;
    int g = lane >> 2, tg = lane & 3;
    int h = blockIdx.z;
    int i0 = blockIdx.y * 128;
    int nd0 = blockIdx.x * 128;
    const float* Ah_g = g_whf + (size_t)((i0 >> 4) * 8 + h) * 8192;
    const float* Al_g = g_wlf + (size_t)((i0 >> 4) * 8 + h) * 8192;
    const float* Bg   = g_vTf + (size_t)(h * 512 + (nd0 >> 3)) * 4096;

    int wi = (wid & 3) * 32, wn = (wid >> 2) * 64;

    float acc[2][8][4];
#pragma unroll
    for (int mt = 0; mt < 2; ++mt)
#pragma unroll
        for (int nt = 0; nt < 8; ++nt)
#pragma unroll
            for (int r = 0; r < 4; ++r) acc[mt][nt][r] = 0.f;

    pw_ldstage(sbase, tid, Ah_g, Al_g, Bg, 0);
    CP_COMMIT();
    pw_ldstage(sbase + PW_STGB, tid, Ah_g, Al_g, Bg, 1);
    CP_COMMIT();

    for (int c = 0; c < 32; ++c) {
        int slot = c % 3;
        if (c + 2 < 32) {
            pw_ldstage(sbase + ((c + 2) % 3) * PW_STGB, tid, Ah_g, Al_g, Bg, c + 2);
            CP_COMMIT();
            CP_WAIT(2);
        } else if (c + 1 < 32) {
            CP_WAIT(1);
        } else {
            CP_WAIT(0);
        }
        __syncthreads();

        const float* Ah = sm + slot * PW_STGF;
        const float* Al = Ah + 2048;
        const float* Bh = Ah + 4096;
#pragma unroll
        for (int kk = 0; kk < 2; ++kk) {
            float4 ahv[2], alv[2];
#pragma unroll
            for (int mt = 0; mt < 2; ++mt) {
                int blk = (((wid & 3) * 2 + mt) * 2 + kk) * 128 + lane * 4;
                ahv[mt] = *(const float4*)(Ah + blk);
                alv[mt] = *(const float4*)(Al + blk);
            }
#pragma unroll
            for (int nt = 0; nt < 8; ++nt) {
                float2 bv = *(const float2*)(Bh + (((wid >> 2) * 8 + nt) * 2 + kk) * 64 + lane * 2);
                uint32_t b0 = __float_as_uint(bv.x);
                uint32_t b1 = __float_as_uint(bv.y);
#pragma unroll
                for (int mt = 0; mt < 2; ++mt) {
                    mma_tf32(acc[mt][nt], (const uint32_t*)&ahv[mt], b0, b1);
                    mma_tf32(acc[mt][nt], (const uint32_t*)&alv[mt], b0, b1);
                }
            }
        }
        __syncthreads();
    }

    // epilogue in two 64-col halves: stage C, gate-multiply, coalesced store
    float* Cs = sm;                       // [64 cols][132 rows]
    size_t obase = ((size_t)h * 4096 + nd0) * 512 + i0;
#pragma unroll
    for (int half = 0; half < 2; ++half) {
        if ((wn >> 6) == half) {
#pragma unroll
            for (int mt = 0; mt < 2; ++mt) {
                int r = wi + mt * 16 + g;
#pragma unroll
                for (int nt = 0; nt < 8; ++nt) {
                    int col = wn + nt * 8 + 2 * tg;
                    int cl = col & 63;
                    Cs[cl * 132 + r]            = acc[mt][nt][0];
                    Cs[(cl + 1) * 132 + r]      = acc[mt][nt][1];
                    Cs[cl * 132 + r + 8]        = acc[mt][nt][2];
                    Cs[(cl + 1) * 132 + r + 8]  = acc[mt][nt][3];
                }
            }
        }
        __syncthreads();
#pragma unroll
        for (int it = 0; it < 8; ++it) {
            int idx = it * 256 + tid;
            int cl = idx >> 5, rq = idx & 31;
            int col = half * 64 + cl;
            float4 ov = *(const float4*)(Cs + cl * 132 + rq * 4);
            float4 gv = *(const float4*)(g_gT + obase + (size_t)col * 512 + rq * 4);
            ov.x *= gv.x; ov.y *= gv.y; ov.z *= gv.z; ov.w *= gv.w;
            *(float4*)(g_o2 + obase + (size_t)col * 512 + rq * 4) = ov;
        }
        __syncthreads();
    }
}

// ---------------------------------------------------------------------------
// Kernel 5: out = (gated o2) @ Wout^T   (gate already applied by pwa)
// ---------------------------------------------------------------------------
__global__ __launch_bounds__(256) void out_kernel(
    const float* __restrict__ Wout, float* __restrict__ out)
{
    __shared__ float As[64 * 128];
    __shared__ float Wt[64 * 64];
    int tid = threadIdx.x;
    int n = blockIdx.x & 511, s0 = (blockIdx.x >> 9) * 128;

#pragma unroll
    for (int it = 0; it < 4; ++it) {
        int idx = it * 256 + tid;
        int c = idx & 63, kq = idx >> 6;
        float4 a = *(const float4*)(Wout + c * 64 + kq * 4);
        Wt[(kq * 4 + 0) * 64 + c] = a.x;
        Wt[(kq * 4 + 1) * 64 + c] = a.y;
        Wt[(kq * 4 + 2) * 64 + c] = a.z;
        Wt[(kq * 4 + 3) * 64 + c] = a.w;
    }

#pragma unroll
    for (int it = 0; it < 8; ++it) {
        int idx = it * 256 + tid;
        int c = idx >> 5, sq = idx & 31;
        *(float4*)(As + c * 128 + sq * 4) =
            *(const float4*)(g_o2 + ((size_t)c * 512 + n) * 512 + s0 + sq * 4);
    }
    __syncthreads();

    int tx = tid & 15, ty = tid >> 4;
    float acc[8][4];
#pragma unroll
    for (int r = 0; r < 8; ++r)
#pragma unroll
        for (int c = 0; c < 4; ++c) acc[r][c] = 0.f;

#pragma unroll
    for (int k = 0; k < 64; ++k) {
        float4 a0 = *(const float4*)(As + k * 128 + ty * 4);
        float4 a1 = *(const float4*)(As + k * 128 + 64 + ty * 4);
        float4 w = *(const float4*)(Wt + k * 64 + tx * 4);
        float a[8] = {a0.x, a0.y, a0.z, a0.w, a1.x, a1.y, a1.z, a1.w};
        float wr[4] = {w.x, w.y, w.z, w.w};
#pragma unroll
        for (int r = 0; r < 8; ++r)
#pragma unroll
            for (int c = 0; c < 4; ++c)
                acc[r][c] = fmaf(a[r], wr[c], acc[r][c]);
    }
#pragma unroll
    for (int rh = 0; rh < 2; ++rh)
#pragma unroll
        for (int rr = 0; rr < 4; ++rr) {
            int orow = rh * 64 + ty * 4 + rr;
            float4 v4 = make_float4(acc[rh * 4 + rr][0], acc[rh * 4 + rr][1],
                                    acc[rh * 4 + rr][2], acc[rh * 4 + rr][3]);
            *(float4*)(out + ((size_t)(s0 + orow) * 512 + n) * CM + tx * 4) = v4;
        }
}

// ---------------------------------------------------------------------------
extern "C" void kernel_launch(void* const* d_in, const int* in_sizes, int n_in,
                              void* d_out, int out_size)
{
    const float* m    = (const float*)d_in[0];
    const float* z    = (const float*)d_in[1];
    const float* lnmw = (const float*)d_in[2];
    const float* lnmb = (const float*)d_in[3];
    const float* lnzw = (const float*)d_in[4];
    const float* lnzb = (const float*)d_in[5];
    const float* Wv   = (const float*)d_in[6];
    const float* Wb   = (const float*)d_in[7];
    const float* Wg   = (const float*)d_in[8];
    const float* Wout = (const float*)d_in[9];
    float* out = (float*)d_out;

    cudaFuncSetAttribute(pwa_mma_kernel,
                         cudaFuncAttributeMaxDynamicSharedMemorySize, PW_SMEMB);
    cudaFuncSetAttribute(vg_kernel,
                         cudaFuncAttributeMaxDynamicSharedMemorySize, VG_SMEMB);
    cudaFuncSetAttribute(softmax_kernel,
                         cudaFuncAttributeMaxDynamicSharedMemorySize, SMX_SMEMB);

    bias_ln_kernel<<<SQ * SQ / 32, 256>>>(z, lnzw, lnzb, Wb);
    softmax_kernel<<<(SQ / 16) * NH, 256, SMX_SMEMB>>>();
    vg_kernel<<<dim3(512, 4), 256, VG_SMEMB>>>(m, lnmw, lnmb, Wv, Wg);
    dim3 gD(32, 4, NH);
    pwa_mma_kernel<<<gD, 256, PW_SMEMB>>>();
    out_kernel<<<SQ * NSEQ / 128, 256>>>(Wout, out);
}

// round 8
// speedup vs baseline: 1.0739x; 1.0739x over previous
#include <cuda_runtime.h>
#include <cstdint>

#define SQ 512
#define NSEQ 512
#define CM 64
#define CZ 128
#define NH 8
#define EPS 1e-5f

// Scratch (device globals: allocation-free)
__device__ float g_w[(size_t)SQ * NH * SQ];        // raw logits [i][h][j]
__device__ float g_whf[(size_t)SQ * NH * SQ];      // w hi, A-frag layout [I][h][jg][lane][4]
__device__ float g_wlf[(size_t)SQ * NH * SQ];      // w lo, same layout
__device__ float g_vTf[(size_t)CM * NSEQ * SQ];    // v, B-frag layout [h][ndg][jg][lane][2]
__device__ float g_gT[(size_t)CM * NSEQ * SQ];     // gate [(c*512+n)*512 + s]
__device__ float g_o2[(size_t)CM * NSEQ * SQ];     // gated o, [(c*512+n)*512 + i]

__device__ __forceinline__ float warp_sum(float v) {
#pragma unroll
    for (int o = 16; o > 0; o >>= 1) v += __shfl_xor_sync(0xffffffffu, v, o);
    return v;
}
__device__ __forceinline__ uint32_t smem_u32(const void* p) {
    uint32_t a;
    asm("{ .reg .u64 t; cvta.to.shared.u64 t, %1; cvt.u32.u64 %0, t; }" : "=r"(a) : "l"(p));
    return a;
}
__device__ __forceinline__ float tf32rn(float x) {
    uint32_t r;
    asm("cvt.rna.tf32.f32 %0, %1;" : "=r"(r) : "f"(x));
    return __uint_as_float(r);
}
__device__ __forceinline__ void mma_tf32(float* d, const uint32_t* a,
                                         uint32_t b0, uint32_t b1) {
    asm volatile(
        "mma.sync.aligned.m16n8k8.row.col.f32.tf32.tf32.f32 "
        "{%0,%1,%2,%3}, {%4,%5,%6,%7}, {%8,%9}, {%0,%1,%2,%3};"
        : "+f"(d[0]), "+f"(d[1]), "+f"(d[2]), "+f"(d[3])
        : "r"(a[0]), "r"(a[1]), "r"(a[2]), "r"(a[3]), "r"(b0), "r"(b1));
}
#define CP_ASYNC16(dst, src) \
    asm volatile("cp.async.cg.shared.global [%0], [%1], 16;" :: "r"(dst), "l"(src))
#define CP_COMMIT() asm volatile("cp.async.commit_group;")
#define CP_WAIT(n)  asm volatile("cp.async.wait_group %0;" :: "n"(n))

// swizzled float index (used by vg phase-2 only)
__device__ __forceinline__ int fidx32(int row, int k) {
    return row * 32 + ((((k >> 2) ^ (row & 7)) << 2) | (k & 3));
}

// ---------------------------------------------------------------------------
// Kernel 1: b[i,h,j] = LN(z[i,j,:]) . W_b[h,:] -> g_w.
// Block: 64 (i,j) rows.  Phase A: warp-LN -> smem.  Phase B: 3-term tf32 mma
// (A = LN(z) 64x128, B = Wb 8x128), partials over k-halves reduced in smem.
// ---------------------------------------------------------------------------
__global__ __launch_bounds__(256) void bias_ln_kernel(
    const float* __restrict__ z, const float* __restrict__ lnw,
    const float* __restrict__ lnb, const float* __restrict__ Wb)
{
    __shared__ float zn[64 * 132];     // normalized z rows (fp32)
    __shared__ float swb[8 * 132];     // Wb padded
    __shared__ float bs[2 * 64 * 8];   // partial logits per k-half
    int tid = threadIdx.x, wid = tid >> 5, lane = tid & 31;
    int g = lane >> 2, tg = lane & 3;

    {   // Wb -> smem (8 rows x 128, pad 132)
        int h = tid >> 5;
        *(float4*)(swb + h * 132 + lane * 4) = *(const float4*)(Wb + h * CZ + lane * 4);
    }
    float4 lw = *(const float4*)(lnw + lane * 4);
    float4 lb = *(const float4*)(lnb + lane * 4);

    size_t R0 = (size_t)blockIdx.x * 64;
#pragma unroll
    for (int rr = 0; rr < 8; ++rr) {
        int row = wid * 8 + rr;
        float4 x = *(const float4*)(z + (R0 + row) * CZ + lane * 4);
        float s = warp_sum(x.x + x.y + x.z + x.w);
        float mu = s * (1.0f / CZ);
        float d0 = x.x - mu, d1 = x.y - mu, d2 = x.z - mu, d3 = x.w - mu;
        float q = warp_sum(d0 * d0 + d1 * d1 + d2 * d2 + d3 * d3);
        float rs = rsqrtf(q * (1.0f / CZ) + EPS);
        float4 nv;
        nv.x = d0 * rs * lw.x + lb.x;
        nv.y = d1 * rs * lw.y + lb.y;
        nv.z = d2 * rs * lw.z + lb.z;
        nv.w = d3 * rs * lw.w + lb.w;
        *(float4*)(zn + row * 132 + lane * 4) = nv;
    }
    __syncthreads();

    {   // Phase B: warp wmt handles m-tile (wid&3), k-half (wid>>2)
        int wmt = wid & 3, kh = wid >> 2;
        float acc[4] = {0.f, 0.f, 0.f, 0.f};
#pragma unroll
        for (int ks = 0; ks < 8; ++ks) {
            int k = kh * 64 + ks * 8;
            float a0 = zn[(wmt * 16 + g) * 132 + k + tg];
            float a1 = zn[(wmt * 16 + g + 8) * 132 + k + tg];
            float a2 = zn[(wmt * 16 + g) * 132 + k + tg + 4];
            float a3 = zn[(wmt * 16 + g + 8) * 132 + k + tg + 4];
            uint32_t ah[4], al[4];
            float h0 = tf32rn(a0), h1 = tf32rn(a1), h2 = tf32rn(a2), h3 = tf32rn(a3);
            ah[0] = __float_as_uint(h0); ah[1] = __float_as_uint(h1);
            ah[2] = __float_as_uint(h2); ah[3] = __float_as_uint(h3);
            al[0] = __float_as_uint(tf32rn(a0 - h0));
            al[1] = __float_as_uint(tf32rn(a1 - h1));
            al[2] = __float_as_uint(tf32rn(a2 - h2));
            al[3] = __float_as_uint(tf32rn(a3 - h3));
            float b0 = swb[g * 132 + k + tg];
            float b1 = swb[g * 132 + k + tg + 4];
            float bh0 = tf32rn(b0), bh1 = tf32rn(b1);
            uint32_t ubh0 = __float_as_uint(bh0), ubh1 = __float_as_uint(bh1);
            uint32_t ubl0 = __float_as_uint(tf32rn(b0 - bh0));
            uint32_t ubl1 = __float_as_uint(tf32rn(b1 - bh1));
            mma_tf32(acc, ah, ubh0, ubh1);
            mma_tf32(acc, al, ubh0, ubh1);
            mma_tf32(acc, ah, ubl0, ubl1);
        }
        int base = kh * 512 + (wmt * 16 + g) * 8 + 2 * tg;
        bs[base] = acc[0];
        bs[base + 1] = acc[1];
        bs[base + 64] = acc[2];      // row +8 -> +8*8
        bs[base + 65] = acc[3];
    }
    __syncthreads();
    {   // Phase C: reduce k-halves, store coalesced
        int h = tid >> 6, row = tid & 63;
        float v = bs[row * 8 + h] + bs[512 + row * 8 + h];
        float v2 = bs[row * 8 + h + 4] + bs[512 + row * 8 + h + 4];
        int i = (int)(R0 >> 9), j0 = (int)(R0 & 511);
        g_w[(size_t)i * 4096 + h * 512 + j0 + row] = v;
        g_w[(size_t)i * 4096 + (h + 4) * 512 + j0 + row] = v2;
    }
}

// ---------------------------------------------------------------------------
// Kernel 2: softmax over j; emits A-fragment-layout hi/lo slabs.
// ---------------------------------------------------------------------------
#define SMX_SMEMB (2 * 8704 * 4)
__global__ __launch_bounds__(256, 1) void softmax_kernel()
{
    extern __shared__ float sx[];
    float* smh = sx;            // [j*17 + i_loc]
    float* sml = sx + 8704;
    int tid = threadIdx.x;
    int row = tid >> 4, l = tid & 15;
    int I = blockIdx.x >> 3, h = blockIdx.x & 7;
    const float* src = g_w + ((size_t)(I * 16 + row)) * 4096 + h * 512;

    float w[32];
    float mx = -1e30f;
#pragma unroll
    for (int jj = 0; jj < 32; ++jj) {
        w[jj] = src[jj * 16 + l];
        mx = fmaxf(mx, w[jj]);
    }
#pragma unroll
    for (int o = 8; o > 0; o >>= 1) mx = fmaxf(mx, __shfl_xor_sync(0xffffffffu, mx, o));
    float sum = 0.f;
#pragma unroll
    for (int jj = 0; jj < 32; ++jj) {
        w[jj] = __expf(w[jj] - mx);
        sum += w[jj];
    }
#pragma unroll
    for (int o = 8; o > 0; o >>= 1) sum += __shfl_xor_sync(0xffffffffu, sum, o);
    float inv = 1.0f / sum;
#pragma unroll
    for (int jj = 0; jj < 32; ++jj) {
        int j = jj * 16 + l;
        float wv = w[jj] * inv;
        float hv = tf32rn(wv);
        smh[j * 17 + row] = hv;
        sml[j * 17 + row] = wv - hv;
    }
    __syncthreads();

    float* dh = g_whf + (size_t)(I * 8 + h) * 8192;
    float* dl = g_wlf + (size_t)(I * 8 + h) * 8192;
#pragma unroll
    for (int it = 0; it < 8; ++it) {
        int u = it * 256 + tid;
        int jg = u >> 5, lane = u & 31;
        float4 vh, vl;
#pragma unroll
        for (int idx = 0; idx < 4; ++idx) {
            int il = (lane >> 2) + (idx & 1) * 8;
            int j = jg * 8 + ((idx >> 1) & 1) * 4 + (lane & 3);
            (&vh.x)[idx] = smh[j * 17 + il];
            (&vl.x)[idx] = sml[j * 17 + il];
        }
        *(float4*)(dh + u * 4) = vh;
        *(float4*)(dl + u * 4) = vl;
    }
}

// ---------------------------------------------------------------------------
// Kernel 3: fused LN(m) -> mma -> vT (B-frag layout) + gate (transposed).
// ---------------------------------------------------------------------------
#define VG_AH 0
#define VG_AL 8192
#define VG_BH 16384
#define VG_SMEMF 24576
#define VG_SMEMB (VG_SMEMF * 4)

__global__ __launch_bounds__(256, 1) void vg_kernel(
    const float* __restrict__ m, const float* __restrict__ lnw,
    const float* __restrict__ lnb, const float* __restrict__ Wv,
    const float* __restrict__ Wg)
{
    extern __shared__ float sm[];
    int tid = threadIdx.x, wid = tid >> 5, lane = tid & 31;
    int g = lane >> 2, tg = lane & 3;
    int n = blockIdx.x, s0 = blockIdx.y * 128;

    {   // phase 1: LN + split to swizzled smem
        int row = tid >> 1, half = tid & 1;
        const float* src = m + ((size_t)(s0 + row) * 512 + n) * CM + half * 32;
        float v[32];
        float s = 0.f, q = 0.f;
#pragma unroll
        for (int qd = 0; qd < 8; ++qd) {
            float4 a = *(const float4*)(src + qd * 4);
            v[qd * 4 + 0] = a.x; v[qd * 4 + 1] = a.y;
            v[qd * 4 + 2] = a.z; v[qd * 4 + 3] = a.w;
            s += a.x + a.y + a.z + a.w;
            q += a.x * a.x + a.y * a.y + a.z * a.z + a.w * a.w;
        }
        s += __shfl_xor_sync(0xffffffffu, s, 1);
        q += __shfl_xor_sync(0xffffffffu, q, 1);
        float mu = s * (1.0f / CM);
        float var = q * (1.0f / CM) - mu * mu;
        float rs = rsqrtf(var + EPS);
#pragma unroll
        for (int qd = 0; qd < 8; ++qd) {
            int kq = half * 8 + qd;
            float xs[4];
#pragma unroll
            for (int t = 0; t < 4; ++t) {
                int k = kq * 4 + t;
                xs[t] = (v[qd * 4 + t] - mu) * rs * __ldg(lnw + k) + __ldg(lnb + k);
            }
            float4 hi = make_float4(tf32rn(xs[0]), tf32rn(xs[1]), tf32rn(xs[2]), tf32rn(xs[3]));
            float4 lo = make_float4(xs[0] - hi.x, xs[1] - hi.y, xs[2] - hi.z, xs[3] - hi.w);
            int f4 = (kq >> 3) * 1024 + row * 8 + ((kq & 7) ^ (row & 7));
            *(float4*)(sm + VG_AH + f4 * 4) = hi;
            *(float4*)(sm + VG_AL + f4 * 4) = lo;
        }
        const float* wsrc = (row < 64) ? (Wv + row * 64) : (Wg + (row - 64) * 64);
#pragma unroll
        for (int qd = 0; qd < 8; ++qd) {
            int kq = half * 8 + qd;
            float4 a = *(const float4*)(wsrc + kq * 4);
            float4 hi = make_float4(tf32rn(a.x), tf32rn(a.y), tf32rn(a.z), tf32rn(a.w));
            int f4 = (kq >> 3) * 1024 + row * 8 + ((kq & 7) ^ (row & 7));
            *(float4*)(sm + VG_BH + f4 * 4) = hi;
        }
    }
    __syncthreads();

    // phase 2: mma
    int wi = (wid & 3) * 32, wn = (wid >> 2) * 64;
    float acc[2][8][4];
#pragma unroll
    for (int mt = 0; mt < 2; ++mt)
#pragma unroll
        for (int nt = 0; nt < 8; ++nt)
#pragma unroll
            for (int r = 0; r < 4; ++r) acc[mt][nt][r] = 0.f;

#pragma unroll
    for (int k8 = 0; k8 < 8; ++k8) {
        int kb = k8 * 8;
        int sec = (kb >> 5) * 4096;
        int kl = kb & 31;
        uint32_t ah[2][4], al[2][4];
#pragma unroll
        for (int mt = 0; mt < 2; ++mt) {
            int r0 = wi + mt * 16 + g;
            ah[mt][0] = __float_as_uint(sm[VG_AH + sec + fidx32(r0, kl + tg)]);
            ah[mt][1] = __float_as_uint(sm[VG_AH + sec + fidx32(r0 + 8, kl + tg)]);
            ah[mt][2] = __float_as_uint(sm[VG_AH + sec + fidx32(r0, kl + 4 + tg)]);
            ah[mt][3] = __float_as_uint(sm[VG_AH + sec + fidx32(r0 + 8, kl + 4 + tg)]);
            al[mt][0] = __float_as_uint(sm[VG_AL + sec + fidx32(r0, kl + tg)]);
            al[mt][1] = __float_as_uint(sm[VG_AL + sec + fidx32(r0 + 8, kl + tg)]);
            al[mt][2] = __float_as_uint(sm[VG_AL + sec + fidx32(r0, kl + 4 + tg)]);
            al[mt][3] = __float_as_uint(sm[VG_AL + sec + fidx32(r0 + 8, kl + 4 + tg)]);
        }
#pragma unroll
        for (int nt = 0; nt < 8; ++nt) {
            int n0 = wn + nt * 8 + g;
            uint32_t b0 = __float_as_uint(sm[VG_BH + sec + fidx32(n0, kl + tg)]);
            uint32_t b1 = __float_as_uint(sm[VG_BH + sec + fidx32(n0, kl + 4 + tg)]);
#pragma unroll
            for (int mt = 0; mt < 2; ++mt) {
                mma_tf32(acc[mt][nt], ah[mt], b0, b1);
                mma_tf32(acc[mt][nt], al[mt], b0, b1);
            }
        }
    }
    __syncthreads();

    // phase 3: epilogue.  Cs = v [c 64][132 rows]; Cg2 = gate [c 64][132 rows]
    float* Cs = sm;
    float* Cg2 = sm + 8448;
#pragma unroll
    for (int mt = 0; mt < 2; ++mt) {
        int r = wi + mt * 16 + g;
#pragma unroll
        for (int nt = 0; nt < 8; ++nt) {
            int col = wn + nt * 8 + 2 * tg;
            if (wid < 4) {
                Cs[col * 132 + r]            = acc[mt][nt][0];
                Cs[(col + 1) * 132 + r]      = acc[mt][nt][1];
                Cs[col * 132 + r + 8]        = acc[mt][nt][2];
                Cs[(col + 1) * 132 + r + 8]  = acc[mt][nt][3];
            } else {
                int cl = col - 64;
                Cg2[cl * 132 + r]            = 1.0f / (1.0f + __expf(-acc[mt][nt][0]));
                Cg2[(cl + 1) * 132 + r]      = 1.0f / (1.0f + __expf(-acc[mt][nt][1]));
                Cg2[cl * 132 + r + 8]        = 1.0f / (1.0f + __expf(-acc[mt][nt][2]));
                Cg2[(cl + 1) * 132 + r + 8]  = 1.0f / (1.0f + __expf(-acc[mt][nt][3]));
            }
        }
    }
    __syncthreads();
    // vT -> B-frag layout: nd = d*512+n; ndg = d*64+(n>>3); gpos = n&7
#pragma unroll
    for (int it = 0; it < 16; ++it) {
        int u = it * 256 + tid;
        int c = u >> 6, rem = u & 63;
        int jgl = rem >> 2, j3 = rem & 3;
        int sl = jgl * 8 + j3;
        float v0 = tf32rn(Cs[c * 132 + sl]);
        float v1 = tf32rn(Cs[c * 132 + sl + 4]);
        int d = c & 7, hh = c >> 3;
        int ndg = d * 64 + (n >> 3);
        int gpos = n & 7;
        size_t off = (((size_t)hh * 512 + ndg) * 64 + (size_t)((s0 >> 3) + jgl)) * 64
                   + (gpos * 4 + j3) * 2;
        *(float2*)(g_vTf + off) = make_float2(v0, v1);
    }
    // gate transposed: g_gT[(c*512+n)*512 + s]
#pragma unroll
    for (int it = 0; it < 8; ++it) {
        int idx = it * 256 + tid;
        int c = idx >> 5, sq = idx & 31;
        *(float4*)(g_gT + ((size_t)c * 512 + n) * 512 + s0 + sq * 4) =
            *(const float4*)(Cg2 + c * 132 + sq * 4);
    }
}

// ---------------------------------------------------------------------------
// Kernel 4: pwa 2-term TF32 mma GEMM (R6 proven config) + gate in epilogue.
// Block 512 thr: M=256(i) x N=128(nd), K=512, kc=32, 2-stage cp.async.
// ---------------------------------------------------------------------------
#define PW_STGB 81920
#define PW_STGF 20480
#define PW_SMEMB (2 * PW_STGB)

__device__ __forceinline__ void pw_ldstage(uint32_t sb, int tid,
                                           const float* Ah_g, const float* Al_g,
                                           const float* Bg, int chunk)
{
    int jg0 = chunk * 4;
#pragma unroll
    for (int it = 0; it < 4; ++it) {
        int t = it * 512 + tid;
        int Igl = t >> 7, rem = t & 127;
        int jgl = rem >> 5, part = rem & 31;
        size_t src = (size_t)Igl * 65536 + (jg0 + jgl) * 128 + part * 4;
        uint32_t d = sb + (uint32_t)t * 16;
        CP_ASYNC16(d, Ah_g + src);
        CP_ASYNC16(d + 32768, Al_g + src);
    }
#pragma unroll
    for (int it = 0; it < 2; ++it) {
        int t = it * 512 + tid;
        int ndgl = t >> 6, rem = t & 63;
        int jgl = rem >> 4, part = rem & 15;
        size_t src = (size_t)ndgl * 4096 + (jg0 + jgl) * 64 + part * 4;
        CP_ASYNC16(sb + 65536 + (uint32_t)t * 16, Bg + src);
    }
}

__global__ __launch_bounds__(512, 1) void pwa_mma_kernel()
{
    extern __shared__ float sm[];
    uint32_t sbase = smem_u32(sm);
    int tid = threadIdx.x, wid = tid >> 5, lane = tid & 31;
    int g = lane >> 2, tg = lane & 3;
    int h = blockIdx.z;
    int i0 = blockIdx.y * 256;
    int nd0 = blockIdx.x * 128;
    const float* Ah_g = g_whf + (size_t)((i0 >> 4) * 8 + h) * 8192;
    const float* Al_g = g_wlf + (size_t)((i0 >> 4) * 8 + h) * 8192;
    const float* Bg   = g_vTf + (size_t)(h * 512 + (nd0 >> 3)) * 4096;

    int iw = (wid & 3) * 4;
    int nw = (wid >> 2) * 4;
    int wi = (wid & 3) * 64, wn = (wid >> 2) * 32;

    float acc[4][4][4];
#pragma unroll
    for (int mt = 0; mt < 4; ++mt)
#pragma unroll
        for (int nt = 0; nt < 4; ++nt)
#pragma unroll
            for (int r = 0; r < 4; ++r) acc[mt][nt][r] = 0.f;

    pw_ldstage(sbase, tid, Ah_g, Al_g, Bg, 0);
    CP_COMMIT();

    for (int c = 0; c < 16; ++c) {
        int buf = c & 1;
        if (c < 15) {
            pw_ldstage(sbase + (buf ^ 1) * PW_STGB, tid, Ah_g, Al_g, Bg, c + 1);
            CP_COMMIT();
            CP_WAIT(1);
        } else {
            CP_WAIT(0);
        }
        __syncthreads();

        const float* Ah = sm + buf * PW_STGF;
        const float* Al = Ah + 8192;
        const float* Bh = Ah + 16384;
#pragma unroll
        for (int kk = 0; kk < 4; ++kk) {
            float4 ahv[4], alv[4];
#pragma unroll
            for (int mt = 0; mt < 4; ++mt) {
                int blk = ((iw + mt) * 4 + kk) * 128 + lane * 4;
                ahv[mt] = *(const float4*)(Ah + blk);
                alv[mt] = *(const float4*)(Al + blk);
            }
#pragma unroll
            for (int nt = 0; nt < 4; ++nt) {
                float2 bv = *(const float2*)(Bh + ((nw + nt) * 4 + kk) * 64 + lane * 2);
                uint32_t b0 = __float_as_uint(bv.x);
                uint32_t b1 = __float_as_uint(bv.y);
#pragma unroll
                for (int mt = 0; mt < 4; ++mt) {
                    mma_tf32(acc[mt][nt], (const uint32_t*)&ahv[mt], b0, b1);
                    mma_tf32(acc[mt][nt], (const uint32_t*)&alv[mt], b0, b1);
                }
            }
        }
        __syncthreads();
    }

    // epilogue: stage C [col 128][260 rows], gate-multiply, coalesced store
    float* Cs = sm;
#pragma unroll
    for (int mt = 0; mt < 4; ++mt) {
        int r = wi + mt * 16 + g;
#pragma unroll
        for (int nt = 0; nt < 4; ++nt) {
            int col = wn + nt * 8 + 2 * tg;
            Cs[col * 260 + r]            = acc[mt][nt][0];
            Cs[(col + 1) * 260 + r]      = acc[mt][nt][1];
            Cs[col * 260 + r + 8]        = acc[mt][nt][2];
            Cs[(col + 1) * 260 + r + 8]  = acc[mt][nt][3];
        }
    }
    __syncthreads();
    size_t obase = ((size_t)h * 4096 + nd0) * 512 + i0;
#pragma unroll
    for (int it = 0; it < 16; ++it) {
        int idx = it * 512 + tid;
        int col = idx >> 6, rq = idx & 63;
        float4 ov = *(const float4*)(Cs + col * 260 + rq * 4);
        float4 gv = *(const float4*)(g_gT + obase + (size_t)col * 512 + rq * 4);
        ov.x *= gv.x; ov.y *= gv.y; ov.z *= gv.z; ov.w *= gv.w;
        *(float4*)(g_o2 + obase + (size_t)col * 512 + rq * 4) = ov;
    }
}

// ---------------------------------------------------------------------------
// Kernel 5: out = (gated o2) @ Wout^T
// ---------------------------------------------------------------------------
__global__ __launch_bounds__(256) void out_kernel(
    const float* __restrict__ Wout, float* __restrict__ out)
{
    __shared__ float As[64 * 128];
    __shared__ float Wt[64 * 64];
    int tid = threadIdx.x;
    int n = blockIdx.x & 511, s0 = (blockIdx.x >> 9) * 128;

#pragma unroll
    for (int it = 0; it < 4; ++it) {
        int idx = it * 256 + tid;
        int c = idx & 63, kq = idx >> 6;
        float4 a = *(const float4*)(Wout + c * 64 + kq * 4);
        Wt[(kq * 4 + 0) * 64 + c] = a.x;
        Wt[(kq * 4 + 1) * 64 + c] = a.y;
        Wt[(kq * 4 + 2) * 64 + c] = a.z;
        Wt[(kq * 4 + 3) * 64 + c] = a.w;
    }

#pragma unroll
    for (int it = 0; it < 8; ++it) {
        int idx = it * 256 + tid;
        int c = idx >> 5, sq = idx & 31;
        *(float4*)(As + c * 128 + sq * 4) =
            *(const float4*)(g_o2 + ((size_t)c * 512 + n) * 512 + s0 + sq * 4);
    }
    __syncthreads();

    int tx = tid & 15, ty = tid >> 4;
    float acc[8][4];
#pragma unroll
    for (int r = 0; r < 8; ++r)
#pragma unroll
        for (int c = 0; c < 4; ++c) acc[r][c] = 0.f;

#pragma unroll
    for (int k = 0; k < 64; ++k) {
        float4 a0 = *(const float4*)(As + k * 128 + ty * 4);
        float4 a1 = *(const float4*)(As + k * 128 + 64 + ty * 4);
        float4 w = *(const float4*)(Wt + k * 64 + tx * 4);
        float a[8] = {a0.x, a0.y, a0.z, a0.w, a1.x, a1.y, a1.z, a1.w};
        float wr[4] = {w.x, w.y, w.z, w.w};
#pragma unroll
        for (int r = 0; r < 8; ++r)
#pragma unroll
            for (int c = 0; c < 4; ++c)
                acc[r][c] = fmaf(a[r], wr[c], acc[r][c]);
    }
#pragma unroll
    for (int rh = 0; rh < 2; ++rh)
#pragma unroll
        for (int rr = 0; rr < 4; ++rr) {
            int orow = rh * 64 + ty * 4 + rr;
            float4 v4 = make_float4(acc[rh * 4 + rr][0], acc[rh * 4 + rr][1],
                                    acc[rh * 4 + rr][2], acc[rh * 4 + rr][3]);
            *(float4*)(out + ((size_t)(s0 + orow) * 512 + n) * CM + tx * 4) = v4;
        }
}

// ---------------------------------------------------------------------------
extern "C" void kernel_launch(void* const* d_in, const int* in_sizes, int n_in,
                              void* d_out, int out_size)
{
    const float* m    = (const float*)d_in[0];
    const float* z    = (const float*)d_in[1];
    const float* lnmw = (const float*)d_in[2];
    const float* lnmb = (const float*)d_in[3];
    const float* lnzw = (const float*)d_in[4];
    const float* lnzb = (const float*)d_in[5];
    const float* Wv   = (const float*)d_in[6];
    const float* Wb   = (const float*)d_in[7];
    const float* Wg   = (const float*)d_in[8];
    const float* Wout = (const float*)d_in[9];
    float* out = (float*)d_out;

    cudaFuncSetAttribute(pwa_mma_kernel,
                         cudaFuncAttributeMaxDynamicSharedMemorySize, PW_SMEMB);
    cudaFuncSetAttribute(vg_kernel,
                         cudaFuncAttributeMaxDynamicSharedMemorySize, VG_SMEMB);
    cudaFuncSetAttribute(softmax_kernel,
                         cudaFuncAttributeMaxDynamicSharedMemorySize, SMX_SMEMB);

    bias_ln_kernel<<<SQ * SQ / 64, 256>>>(z, lnzw, lnzb, Wb);
    softmax_kernel<<<(SQ / 16) * NH, 256, SMX_SMEMB>>>();
    vg_kernel<<<dim3(512, 4), 256, VG_SMEMB>>>(m, lnmw, lnmb, Wv, Wg);
    dim3 gD(32, 2, NH);
    pwa_mma_kernel<<<gD, 512, PW_SMEMB>>>();
    out_kernel<<<SQ * NSEQ / 128, 256>>>(Wout, out);
}

// round 9
// speedup vs baseline: 1.2597x; 1.1730x over previous
#include <cuda_runtime.h>
#include <cstdint>

#define SQ 512
#define NSEQ 512
#define CM 64
#define CZ 128
#define NH 8
#define EPS 1e-5f

// Scratch (device globals: allocation-free)
__device__ float g_w[(size_t)SQ * NH * SQ];        // raw logits [i][h][j]
__device__ float g_whf[(size_t)SQ * NH * SQ];      // w hi, A-frag layout [I][h][jg][lane][4]
__device__ float g_vTf[(size_t)CM * NSEQ * SQ];    // v, B-frag layout [h][ndg][jg][lane][2]
__device__ float g_gT[(size_t)CM * NSEQ * SQ];     // gate [(c*512+n)*512 + s]
__device__ float g_o2[(size_t)CM * NSEQ * SQ];     // gated o, [(c*512+n)*512 + i]

__device__ __forceinline__ float warp_sum(float v) {
#pragma unroll
    for (int o = 16; o > 0; o >>= 1) v += __shfl_xor_sync(0xffffffffu, v, o);
    return v;
}
__device__ __forceinline__ uint32_t smem_u32(const void* p) {
    uint32_t a;
    asm("{ .reg .u64 t; cvta.to.shared.u64 t, %1; cvt.u32.u64 %0, t; }" : "=r"(a) : "l"(p));
    return a;
}
__device__ __forceinline__ float tf32rn(float x) {
    uint32_t r;
    asm("cvt.rna.tf32.f32 %0, %1;" : "=r"(r) : "f"(x));
    return __uint_as_float(r);
}
__device__ __forceinline__ void mma_tf32(float* d, const uint32_t* a,
                                         uint32_t b0, uint32_t b1) {
    asm volatile(
        "mma.sync.aligned.m16n8k8.row.col.f32.tf32.tf32.f32 "
        "{%0,%1,%2,%3}, {%4,%5,%6,%7}, {%8,%9}, {%0,%1,%2,%3};"
        : "+f"(d[0]), "+f"(d[1]), "+f"(d[2]), "+f"(d[3])
        : "r"(a[0]), "r"(a[1]), "r"(a[2]), "r"(a[3]), "r"(b0), "r"(b1));
}
#define CP_ASYNC16(dst, src) \
    asm volatile("cp.async.cg.shared.global [%0], [%1], 16;" :: "r"(dst), "l"(src))
#define CP_COMMIT() asm volatile("cp.async.commit_group;")
#define CP_WAIT(n)  asm volatile("cp.async.wait_group %0;" :: "n"(n))

// swizzled float index (used by vg phase-2 only)
__device__ __forceinline__ int fidx32(int row, int k) {
    return row * 32 + ((((k >> 2) ^ (row & 7)) << 2) | (k & 3));
}

// ---------------------------------------------------------------------------
// Kernel 1: b[i,h,j] = LN(z[i,j,:]) . W_b[h,:] -> g_w.  (R8 version, proven)
// ---------------------------------------------------------------------------
__global__ __launch_bounds__(256) void bias_ln_kernel(
    const float* __restrict__ z, const float* __restrict__ lnw,
    const float* __restrict__ lnb, const float* __restrict__ Wb)
{
    __shared__ float zn[64 * 132];
    __shared__ float swb[8 * 132];
    __shared__ float bs[2 * 64 * 8];
    int tid = threadIdx.x, wid = tid >> 5, lane = tid & 31;
    int g = lane >> 2, tg = lane & 3;

    {
        int h = tid >> 5;
        *(float4*)(swb + h * 132 + lane * 4) = *(const float4*)(Wb + h * CZ + lane * 4);
    }
    float4 lw = *(const float4*)(lnw + lane * 4);
    float4 lb = *(const float4*)(lnb + lane * 4);

    size_t R0 = (size_t)blockIdx.x * 64;
#pragma unroll
    for (int rr = 0; rr < 8; ++rr) {
        int row = wid * 8 + rr;
        float4 x = *(const float4*)(z + (R0 + row) * CZ + lane * 4);
        float s = warp_sum(x.x + x.y + x.z + x.w);
        float mu = s * (1.0f / CZ);
        float d0 = x.x - mu, d1 = x.y - mu, d2 = x.z - mu, d3 = x.w - mu;
        float q = warp_sum(d0 * d0 + d1 * d1 + d2 * d2 + d3 * d3);
        float rs = rsqrtf(q * (1.0f / CZ) + EPS);
        float4 nv;
        nv.x = d0 * rs * lw.x + lb.x;
        nv.y = d1 * rs * lw.y + lb.y;
        nv.z = d2 * rs * lw.z + lb.z;
        nv.w = d3 * rs * lw.w + lb.w;
        *(float4*)(zn + row * 132 + lane * 4) = nv;
    }
    __syncthreads();

    {
        int wmt = wid & 3, kh = wid >> 2;
        float acc[4] = {0.f, 0.f, 0.f, 0.f};
#pragma unroll
        for (int ks = 0; ks < 8; ++ks) {
            int k = kh * 64 + ks * 8;
            float a0 = zn[(wmt * 16 + g) * 132 + k + tg];
            float a1 = zn[(wmt * 16 + g + 8) * 132 + k + tg];
            float a2 = zn[(wmt * 16 + g) * 132 + k + tg + 4];
            float a3 = zn[(wmt * 16 + g + 8) * 132 + k + tg + 4];
            uint32_t ah[4], al[4];
            float h0 = tf32rn(a0), h1 = tf32rn(a1), h2 = tf32rn(a2), h3 = tf32rn(a3);
            ah[0] = __float_as_uint(h0); ah[1] = __float_as_uint(h1);
            ah[2] = __float_as_uint(h2); ah[3] = __float_as_uint(h3);
            al[0] = __float_as_uint(tf32rn(a0 - h0));
            al[1] = __float_as_uint(tf32rn(a1 - h1));
            al[2] = __float_as_uint(tf32rn(a2 - h2));
            al[3] = __float_as_uint(tf32rn(a3 - h3));
            float b0 = swb[g * 132 + k + tg];
            float b1 = swb[g * 132 + k + tg + 4];
            float bh0 = tf32rn(b0), bh1 = tf32rn(b1);
            uint32_t ubh0 = __float_as_uint(bh0), ubh1 = __float_as_uint(bh1);
            uint32_t ubl0 = __float_as_uint(tf32rn(b0 - bh0));
            uint32_t ubl1 = __float_as_uint(tf32rn(b1 - bh1));
            mma_tf32(acc, ah, ubh0, ubh1);
            mma_tf32(acc, al, ubh0, ubh1);
            mma_tf32(acc, ah, ubl0, ubl1);
        }
        int base = kh * 512 + (wmt * 16 + g) * 8 + 2 * tg;
        bs[base] = acc[0];
        bs[base + 1] = acc[1];
        bs[base + 64] = acc[2];
        bs[base + 65] = acc[3];
    }
    __syncthreads();
    {
        int h = tid >> 6, row = tid & 63;
        float v = bs[row * 8 + h] + bs[512 + row * 8 + h];
        float v2 = bs[row * 8 + h + 4] + bs[512 + row * 8 + h + 4];
        int i = (int)(R0 >> 9), j0 = (int)(R0 & 511);
        g_w[(size_t)i * 4096 + h * 512 + j0 + row] = v;
        g_w[(size_t)i * 4096 + (h + 4) * 512 + j0 + row] = v2;
    }
}

// ---------------------------------------------------------------------------
// Kernel 2: softmax over j; emits A-fragment-layout hi slab only (1-term w).
// ---------------------------------------------------------------------------
#define SMX_SMEMB (8704 * 4)
__global__ __launch_bounds__(256, 1) void softmax_kernel()
{
    extern __shared__ float sx[];
    float* smh = sx;            // [j*17 + i_loc]
    int tid = threadIdx.x;
    int row = tid >> 4, l = tid & 15;
    int I = blockIdx.x >> 3, h = blockIdx.x & 7;
    const float* src = g_w + ((size_t)(I * 16 + row)) * 4096 + h * 512;

    float w[32];
    float mx = -1e30f;
#pragma unroll
    for (int jj = 0; jj < 32; ++jj) {
        w[jj] = src[jj * 16 + l];
        mx = fmaxf(mx, w[jj]);
    }
#pragma unroll
    for (int o = 8; o > 0; o >>= 1) mx = fmaxf(mx, __shfl_xor_sync(0xffffffffu, mx, o));
    float sum = 0.f;
#pragma unroll
    for (int jj = 0; jj < 32; ++jj) {
        w[jj] = __expf(w[jj] - mx);
        sum += w[jj];
    }
#pragma unroll
    for (int o = 8; o > 0; o >>= 1) sum += __shfl_xor_sync(0xffffffffu, sum, o);
    float inv = 1.0f / sum;
#pragma unroll
    for (int jj = 0; jj < 32; ++jj) {
        int j = jj * 16 + l;
        smh[j * 17 + row] = tf32rn(w[jj] * inv);
    }
    __syncthreads();

    float* dh = g_whf + (size_t)(I * 8 + h) * 8192;
#pragma unroll
    for (int it = 0; it < 8; ++it) {
        int u = it * 256 + tid;
        int jg = u >> 5, lane = u & 31;
        float4 vh;
#pragma unroll
        for (int idx = 0; idx < 4; ++idx) {
            int il = (lane >> 2) + (idx & 1) * 8;
            int j = jg * 8 + ((idx >> 1) & 1) * 4 + (lane & 3);
            (&vh.x)[idx] = smh[j * 17 + il];
        }
        *(float4*)(dh + u * 4) = vh;
    }
}

// ---------------------------------------------------------------------------
// Kernel 3: fused LN(m) -> mma -> vT (B-frag layout) + gate (transposed).
// (R8 version, unchanged)
// ---------------------------------------------------------------------------
#define VG_AH 0
#define VG_AL 8192
#define VG_BH 16384
#define VG_SMEMF 24576
#define VG_SMEMB (VG_SMEMF * 4)

__global__ __launch_bounds__(256, 1) void vg_kernel(
    const float* __restrict__ m, const float* __restrict__ lnw,
    const float* __restrict__ lnb, const float* __restrict__ Wv,
    const float* __restrict__ Wg)
{
    extern __shared__ float sm[];
    int tid = threadIdx.x, wid = tid >> 5, lane = tid & 31;
    int g = lane >> 2, tg = lane & 3;
    int n = blockIdx.x, s0 = blockIdx.y * 128;

    {
        int row = tid >> 1, half = tid & 1;
        const float* src = m + ((size_t)(s0 + row) * 512 + n) * CM + half * 32;
        float v[32];
        float s = 0.f, q = 0.f;
#pragma unroll
        for (int qd = 0; qd < 8; ++qd) {
            float4 a = *(const float4*)(src + qd * 4);
            v[qd * 4 + 0] = a.x; v[qd * 4 + 1] = a.y;
            v[qd * 4 + 2] = a.z; v[qd * 4 + 3] = a.w;
            s += a.x + a.y + a.z + a.w;
            q += a.x * a.x + a.y * a.y + a.z * a.z + a.w * a.w;
        }
        s += __shfl_xor_sync(0xffffffffu, s, 1);
        q += __shfl_xor_sync(0xffffffffu, q, 1);
        float mu = s * (1.0f / CM);
        float var = q * (1.0f / CM) - mu * mu;
        float rs = rsqrtf(var + EPS);
#pragma unroll
        for (int qd = 0; qd < 8; ++qd) {
            int kq = half * 8 + qd;
            float xs[4];
#pragma unroll
            for (int t = 0; t < 4; ++t) {
                int k = kq * 4 + t;
                xs[t] = (v[qd * 4 + t] - mu) * rs * __ldg(lnw + k) + __ldg(lnb + k);
            }
            float4 hi = make_float4(tf32rn(xs[0]), tf32rn(xs[1]), tf32rn(xs[2]), tf32rn(xs[3]));
            float4 lo = make_float4(xs[0] - hi.x, xs[1] - hi.y, xs[2] - hi.z, xs[3] - hi.w);
            int f4 = (kq >> 3) * 1024 + row * 8 + ((kq & 7) ^ (row & 7));
            *(float4*)(sm + VG_AH + f4 * 4) = hi;
            *(float4*)(sm + VG_AL + f4 * 4) = lo;
        }
        const float* wsrc = (row < 64) ? (Wv + row * 64) : (Wg + (row - 64) * 64);
#pragma unroll
        for (int qd = 0; qd < 8; ++qd) {
            int kq = half * 8 + qd;
            float4 a = *(const float4*)(wsrc + kq * 4);
            float4 hi = make_float4(tf32rn(a.x), tf32rn(a.y), tf32rn(a.z), tf32rn(a.w));
            int f4 = (kq >> 3) * 1024 + row * 8 + ((kq & 7) ^ (row & 7));
            *(float4*)(sm + VG_BH + f4 * 4) = hi;
        }
    }
    __syncthreads();

    int wi = (wid & 3) * 32, wn = (wid >> 2) * 64;
    float acc[2][8][4];
#pragma unroll
    for (int mt = 0; mt < 2; ++mt)
#pragma unroll
        for (int nt = 0; nt < 8; ++nt)
#pragma unroll
            for (int r = 0; r < 4; ++r) acc[mt][nt][r] = 0.f;

#pragma unroll
    for (int k8 = 0; k8 < 8; ++k8) {
        int kb = k8 * 8;
        int sec = (kb >> 5) * 4096;
        int kl = kb & 31;
        uint32_t ah[2][4], al[2][4];
#pragma unroll
        for (int mt = 0; mt < 2; ++mt) {
            int r0 = wi + mt * 16 + g;
            ah[mt][0] = __float_as_uint(sm[VG_AH + sec + fidx32(r0, kl + tg)]);
            ah[mt][1] = __float_as_uint(sm[VG_AH + sec + fidx32(r0 + 8, kl + tg)]);
            ah[mt][2] = __float_as_uint(sm[VG_AH + sec + fidx32(r0, kl + 4 + tg)]);
            ah[mt][3] = __float_as_uint(sm[VG_AH + sec + fidx32(r0 + 8, kl + 4 + tg)]);
            al[mt][0] = __float_as_uint(sm[VG_AL + sec + fidx32(r0, kl + tg)]);
            al[mt][1] = __float_as_uint(sm[VG_AL + sec + fidx32(r0 + 8, kl + tg)]);
            al[mt][2] = __float_as_uint(sm[VG_AL + sec + fidx32(r0, kl + 4 + tg)]);
            al[mt][3] = __float_as_uint(sm[VG_AL + sec + fidx32(r0 + 8, kl + 4 + tg)]);
        }
#pragma unroll
        for (int nt = 0; nt < 8; ++nt) {
            int n0 = wn + nt * 8 + g;
            uint32_t b0 = __float_as_uint(sm[VG_BH + sec + fidx32(n0, kl + tg)]);
            uint32_t b1 = __float_as_uint(sm[VG_BH + sec + fidx32(n0, kl + 4 + tg)]);
#pragma unroll
            for (int mt = 0; mt < 2; ++mt) {
                mma_tf32(acc[mt][nt], ah[mt], b0, b1);
                mma_tf32(acc[mt][nt], al[mt], b0, b1);
            }
        }
    }
    __syncthreads();

    float* Cs = sm;
    float* Cg2 = sm + 8448;
#pragma unroll
    for (int mt = 0; mt < 2; ++mt) {
        int r = wi + mt * 16 + g;
#pragma unroll
        for (int nt = 0; nt < 8; ++nt) {
            int col = wn + nt * 8 + 2 * tg;
            if (wid < 4) {
                Cs[col * 132 + r]            = acc[mt][nt][0];
                Cs[(col + 1) * 132 + r]      = acc[mt][nt][1];
                Cs[col * 132 + r + 8]        = acc[mt][nt][2];
                Cs[(col + 1) * 132 + r + 8]  = acc[mt][nt][3];
            } else {
                int cl = col - 64;
                Cg2[cl * 132 + r]            = 1.0f / (1.0f + __expf(-acc[mt][nt][0]));
                Cg2[(cl + 1) * 132 + r]      = 1.0f / (1.0f + __expf(-acc[mt][nt][1]));
                Cg2[cl * 132 + r + 8]        = 1.0f / (1.0f + __expf(-acc[mt][nt][2]));
                Cg2[(cl + 1) * 132 + r + 8]  = 1.0f / (1.0f + __expf(-acc[mt][nt][3]));
            }
        }
    }
    __syncthreads();
#pragma unroll
    for (int it = 0; it < 16; ++it) {
        int u = it * 256 + tid;
        int c = u >> 6, rem = u & 63;
        int jgl = rem >> 2, j3 = rem & 3;
        int sl = jgl * 8 + j3;
        float v0 = tf32rn(Cs[c * 132 + sl]);
        float v1 = tf32rn(Cs[c * 132 + sl + 4]);
        int d = c & 7, hh = c >> 3;
        int ndg = d * 64 + (n >> 3);
        int gpos = n & 7;
        size_t off = (((size_t)hh * 512 + ndg) * 64 + (size_t)((s0 >> 3) + jgl)) * 64
                   + (gpos * 4 + j3) * 2;
        *(float2*)(g_vTf + off) = make_float2(v0, v1);
    }
#pragma unroll
    for (int it = 0; it < 8; ++it) {
        int idx = it * 256 + tid;
        int c = idx >> 5, sq = idx & 31;
        *(float4*)(g_gT + ((size_t)c * 512 + n) * 512 + s0 + sq * 4) =
            *(const float4*)(Cg2 + c * 132 + sq * 4);
    }
}

// ---------------------------------------------------------------------------
// Kernel 4: pwa 1-term TF32 mma GEMM, 3-stage cp.async, gate in epilogue.
// Block 512 thr: M=256(i) x N=128(nd), K=512, kc=32.
// Stage (floats): A 8192 | B 4096 = 48KB; 3 stages = 144KB.
// ---------------------------------------------------------------------------
#define PW_STGF 12288
#define PW_STGB 49152
#define PW_SMEMB (3 * PW_STGB)

__device__ __forceinline__ void pw_ldstage(uint32_t sb, int tid,
                                           const float* Ah_g, const float* Bg,
                                           int chunk)
{
    int jg0 = chunk * 4;
#pragma unroll
    for (int it = 0; it < 4; ++it) {       // A: 2048 float4
        int t = it * 512 + tid;
        int Igl = t >> 7, rem = t & 127;
        int jgl = rem >> 5, part = rem & 31;
        size_t src = (size_t)Igl * 65536 + (jg0 + jgl) * 128 + part * 4;
        CP_ASYNC16(sb + (uint32_t)t * 16, Ah_g + src);
    }
#pragma unroll
    for (int it = 0; it < 2; ++it) {       // B: 1024 float4
        int t = it * 512 + tid;
        int ndgl = t >> 6, rem = t & 63;
        int jgl = rem >> 4, part = rem & 15;
        size_t src = (size_t)ndgl * 4096 + (jg0 + jgl) * 64 + part * 4;
        CP_ASYNC16(sb + 32768 + (uint32_t)t * 16, Bg + src);
    }
}

__global__ __launch_bounds__(512, 1) void pwa_mma_kernel()
{
    extern __shared__ float sm[];
    uint32_t sbase = smem_u32(sm);
    int tid = threadIdx.x, wid = tid >> 5, lane = tid & 31;
    int g = lane >> 2, tg = lane & 3;
    int h = blockIdx.z;
    int i0 = blockIdx.y * 256;
    int nd0 = blockIdx.x * 128;
    const float* Ah_g = g_whf + (size_t)((i0 >> 4) * 8 + h) * 8192;
    const float* Bg   = g_vTf + (size_t)(h * 512 + (nd0 >> 3)) * 4096;

    int iw = (wid & 3) * 4;
    int nw = (wid >> 2) * 4;
    int wi = (wid & 3) * 64, wn = (wid >> 2) * 32;

    float acc[4][4][4];
#pragma unroll
    for (int mt = 0; mt < 4; ++mt)
#pragma unroll
        for (int nt = 0; nt < 4; ++nt)
#pragma unroll
            for (int r = 0; r < 4; ++r) acc[mt][nt][r] = 0.f;

    pw_ldstage(sbase, tid, Ah_g, Bg, 0);
    CP_COMMIT();
    pw_ldstage(sbase + PW_STGB, tid, Ah_g, Bg, 1);
    CP_COMMIT();

    for (int c = 0; c < 16; ++c) {
        int slot = c % 3;
        if (c + 2 < 16) {
            pw_ldstage(sbase + ((c + 2) % 3) * PW_STGB, tid, Ah_g, Bg, c + 2);
            CP_COMMIT();
            CP_WAIT(2);
        } else if (c + 1 < 16) {
            CP_WAIT(1);
        } else {
            CP_WAIT(0);
        }
        __syncthreads();

        const float* Ah = sm + slot * PW_STGF;
        const float* Bh = Ah + 8192;
#pragma unroll
        for (int kk = 0; kk < 4; ++kk) {
            float4 ahv[4];
#pragma unroll
            for (int mt = 0; mt < 4; ++mt) {
                int blk = ((iw + mt) * 4 + kk) * 128 + lane * 4;
                ahv[mt] = *(const float4*)(Ah + blk);
            }
#pragma unroll
            for (int nt = 0; nt < 4; ++nt) {
                float2 bv = *(const float2*)(Bh + ((nw + nt) * 4 + kk) * 64 + lane * 2);
                uint32_t b0 = __float_as_uint(bv.x);
                uint32_t b1 = __float_as_uint(bv.y);
#pragma unroll
                for (int mt = 0; mt < 4; ++mt)
                    mma_tf32(acc[mt][nt], (const uint32_t*)&ahv[mt], b0, b1);
            }
        }
        __syncthreads();
    }

    // epilogue: stage C [col 128][260 rows], gate-multiply, coalesced store
    float* Cs = sm;
#pragma unroll
    for (int mt = 0; mt < 4; ++mt) {
        int r = wi + mt * 16 + g;
#pragma unroll
        for (int nt = 0; nt < 4; ++nt) {
            int col = wn + nt * 8 + 2 * tg;
            Cs[col * 260 + r]            = acc[mt][nt][0];
            Cs[(col + 1) * 260 + r]      = acc[mt][nt][1];
            Cs[col * 260 + r + 8]        = acc[mt][nt][2];
            Cs[(col + 1) * 260 + r + 8]  = acc[mt][nt][3];
        }
    }
    __syncthreads();
    size_t obase = ((size_t)h * 4096 + nd0) * 512 + i0;
#pragma unroll
    for (int it = 0; it < 16; ++it) {
        int idx = it * 512 + tid;
        int col = idx >> 6, rq = idx & 63;
        float4 ov = *(const float4*)(Cs + col * 260 + rq * 4);
        float4 gv = *(const float4*)(g_gT + obase + (size_t)col * 512 + rq * 4);
        ov.x *= gv.x; ov.y *= gv.y; ov.z *= gv.z; ov.w *= gv.w;
        *(float4*)(g_o2 + obase + (size_t)col * 512 + rq * 4) = ov;
    }
}

// ---------------------------------------------------------------------------
// Kernel 5: out = (gated o2) @ Wout^T
// ---------------------------------------------------------------------------
__global__ __launch_bounds__(256) void out_kernel(
    const float* __restrict__ Wout, float* __restrict__ out)
{
    __shared__ float As[64 * 128];
    __shared__ float Wt[64 * 64];
    int tid = threadIdx.x;
    int n = blockIdx.x & 511, s0 = (blockIdx.x >> 9) * 128;

#pragma unroll
    for (int it = 0; it < 4; ++it) {
        int idx = it * 256 + tid;
        int c = idx & 63, kq = idx >> 6;
        float4 a = *(const float4*)(Wout + c * 64 + kq * 4);
        Wt[(kq * 4 + 0) * 64 + c] = a.x;
        Wt[(kq * 4 + 1) * 64 + c] = a.y;
        Wt[(kq * 4 + 2) * 64 + c] = a.z;
        Wt[(kq * 4 + 3) * 64 + c] = a.w;
    }

#pragma unroll
    for (int it = 0; it < 8; ++it) {
        int idx = it * 256 + tid;
        int c = idx >> 5, sq = idx & 31;
        *(float4*)(As + c * 128 + sq * 4) =
            *(const float4*)(g_o2 + ((size_t)c * 512 + n) * 512 + s0 + sq * 4);
    }
    __syncthreads();

    int tx = tid & 15, ty = tid >> 4;
    float acc[8][4];
#pragma unroll
    for (int r = 0; r < 8; ++r)
#pragma unroll
        for (int c = 0; c < 4; ++c) acc[r][c] = 0.f;

#pragma unroll
    for (int k = 0; k < 64; ++k) {
        float4 a0 = *(const float4*)(As + k * 128 + ty * 4);
        float4 a1 = *(const float4*)(As + k * 128 + 64 + ty * 4);
        float4 w = *(const float4*)(Wt + k * 64 + tx * 4);
        float a[8] = {a0.x, a0.y, a0.z, a0.w, a1.x, a1.y, a1.z, a1.w};
        float wr[4] = {w.x, w.y, w.z, w.w};
#pragma unroll
        for (int r = 0; r < 8; ++r)
#pragma unroll
            for (int c = 0; c < 4; ++c)
                acc[r][c] = fmaf(a[r], wr[c], acc[r][c]);
    }
#pragma unroll
    for (int rh = 0; rh < 2; ++rh)
#pragma unroll
        for (int rr = 0; rr < 4; ++rr) {
            int orow = rh * 64 + ty * 4 + rr;
            float4 v4 = make_float4(acc[rh * 4 + rr][0], acc[rh * 4 + rr][1],
                                    acc[rh * 4 + rr][2], acc[rh * 4 + rr][3]);
            *(float4*)(out + ((size_t)(s0 + orow) * 512 + n) * CM + tx * 4) = v4;
        }
}

// ---------------------------------------------------------------------------
extern "C" void kernel_launch(void* const* d_in, const int* in_sizes, int n_in,
                              void* d_out, int out_size)
{
    const float* m    = (const float*)d_in[0];
    const float* z    = (const float*)d_in[1];
    const float* lnmw = (const float*)d_in[2];
    const float* lnmb = (const float*)d_in[3];
    const float* lnzw = (const float*)d_in[4];
    const float* lnzb = (const float*)d_in[5];
    const float* Wv   = (const float*)d_in[6];
    const float* Wb   = (const float*)d_in[7];
    const float* Wg   = (const float*)d_in[8];
    const float* Wout = (const float*)d_in[9];
    float* out = (float*)d_out;

    cudaFuncSetAttribute(pwa_mma_kernel,
                         cudaFuncAttributeMaxDynamicSharedMemorySize, PW_SMEMB);
    cudaFuncSetAttribute(vg_kernel,
                         cudaFuncAttributeMaxDynamicSharedMemorySize, VG_SMEMB);
    cudaFuncSetAttribute(softmax_kernel,
                         cudaFuncAttributeMaxDynamicSharedMemorySize, SMX_SMEMB);

    bias_ln_kernel<<<SQ * SQ / 64, 256>>>(z, lnzw, lnzb, Wb);
    softmax_kernel<<<(SQ / 16) * NH, 256, SMX_SMEMB>>>();
    vg_kernel<<<dim3(512, 4), 256, VG_SMEMB>>>(m, lnmw, lnmb, Wv, Wg);
    dim3 gD(32, 2, NH);
    pwa_mma_kernel<<<gD, 512, PW_SMEMB>>>();
    out_kernel<<<SQ * NSEQ / 128, 256>>>(Wout, out);
}